// round 14
// baseline (speedup 1.0000x reference)
#include <cuda_runtime.h>

// Problem constants
#define BB 16
#define NL 4097          // x0 rows per batch
#define NM 1024          // p_m rows
#define DS 256
#define DM 512
#define DL 1024
#define NKV 4098         // cls + NL
#define NCHUNK 64        // big covers 64*64 = 4096 rows; row 4096 handled in u_kernel
#define MCH 32           // m-chunks for transposed gemv

// PDL device hooks
#define GRID_WAIT()       asm volatile("griddepcontrol.wait;" ::: "memory")
#define GRID_LAUNCH_DEP() asm volatile("griddepcontrol.launch_dependents;" ::: "memory")

// ---------------- device scratch ----------------
__device__ float g_csp  [BB*DM];
__device__ float g_q1   [BB*DM];
__device__ float g_qk1  [BB*DM];
__device__ float g_cmp  [BB*DL];
__device__ float g_q2   [BB*DL];
__device__ float g_qk2  [BB*DL];
__device__ float g_sc1  [BB*(NM+1)];
__device__ float g_att1s[BB*(NM+1)];
__device__ float g_a1p  [BB*NKV];
__device__ float g_PE   [BB*NCHUNK*DL];
__device__ float g_PA   [BB*NCHUNK*DL];
__device__ float g_PZ   [BB*NCHUNK];
__device__ float g_u    [BB*DL];
__device__ float g_outv [BB*DL];
__device__ float g_gs   [BB*DS];
__device__ float g_part1[MCH*BB*DM];
__device__ float g_part2[MCH*BB*DL];

// ---------------- multi-batch GEMV: Y[b,m] = bias[m] + W[m,:]·X[b,:] ----------------
__global__ __launch_bounds__(256) void gemvA_kernel(
    const float* __restrict__ W, const float* __restrict__ X, int ldx4,
    const float* __restrict__ bias, float* __restrict__ Y, int M, int D)
{
    GRID_WAIT();
    int m = blockIdx.x * 8 + (threadIdx.x >> 5);
    int lane = threadIdx.x & 31;
    if (m < M) {
        const float4* w4 = (const float4*)(W + (size_t)m * D);
        const float4* x4 = (const float4*)X;
        int D4 = D >> 2;
        float acc[BB];
#pragma unroll
        for (int b = 0; b < BB; b++) acc[b] = 0.f;
        for (int f = lane; f < D4; f += 32) {
            float4 w = w4[f];
#pragma unroll
            for (int b = 0; b < BB; b++) {
                float4 x = x4[(size_t)b * ldx4 + f];
                acc[b] += w.x*x.x + w.y*x.y + w.z*x.z + w.w*x.w;
            }
        }
#pragma unroll
        for (int b = 0; b < BB; b++) {
            float v = acc[b];
#pragma unroll
            for (int o = 16; o; o >>= 1) v += __shfl_xor_sync(~0u, v, o);
            if (lane == 0) Y[(size_t)b * M + m] = v + (bias ? bias[m] : 0.f);
        }
    }
    GRID_LAUNCH_DEP();
}

// ---------------- transposed GEMV partials: part[my][b][d] ----------------
__global__ __launch_bounds__(256) void gemvB_kernel(
    const float* __restrict__ W, const float* __restrict__ X,
    float* __restrict__ part, int M, int D)
{
    GRID_WAIT();
    int d = blockIdx.x * 256 + threadIdx.x;
    int rows = M / MCH;                 // 16 or 32
    int m0 = blockIdx.y * rows;
    __shared__ float q[BB * 32];
    for (int idx = threadIdx.x; idx < BB * rows; idx += 256) {
        int bb = idx / rows, mm = idx - bb * rows;
        q[bb * rows + mm] = X[(size_t)bb * M + m0 + mm];
    }
    __syncthreads();
    float acc[BB];
#pragma unroll
    for (int b = 0; b < BB; b++) acc[b] = 0.f;
    for (int mm = 0; mm < rows; mm++) {
        float w = W[(size_t)(m0 + mm) * D + d];
#pragma unroll
        for (int b = 0; b < BB; b++) acc[b] += w * q[b * rows + mm];
    }
#pragma unroll
    for (int b = 0; b < BB; b++)
        part[((size_t)blockIdx.y * BB + b) * D + d] = acc[b];
    GRID_LAUNCH_DEP();
}

__global__ __launch_bounds__(256) void gemvBred_kernel(
    const float* __restrict__ part, float* __restrict__ Y, int D)
{
    GRID_WAIT();
    int t = blockIdx.x * 256 + threadIdx.x;
    int b = t / D, d = t - b * D;
    float acc = 0.f;
#pragma unroll
    for (int c = 0; c < MCH; c++) acc += part[((size_t)c * BB + b) * D + d];
    Y[t] = acc;
    GRID_LAUNCH_DEP();
}

// ---------------- att1 scores over p_m: 4 rows per warp, batched shfl reduce ----------------
__global__ __launch_bounds__(256) void score1_kernel(const float* __restrict__ x1)
{
    GRID_WAIT();
    int gw = (blockIdx.x * 256 + threadIdx.x) >> 5;
    int lane = threadIdx.x & 31;
    int rr = gw * 4;
    int b = rr >> 10, k0 = rr & 1023;
    const float4* qk = (const float4*)(g_qk1 + (size_t)b * DM);
    float4 q[4];
#pragma unroll
    for (int j = 0; j < 4; j++) q[j] = qk[lane + 32 * j];
    float s[4] = {0.f, 0.f, 0.f, 0.f};
#pragma unroll
    for (int i = 0; i < 4; i++) {
        const float4* row = (const float4*)(x1 + ((size_t)b * (NM + 1) + 1 + k0 + i) * DM);
#pragma unroll
        for (int j = 0; j < 4; j++) {
            float4 v = __ldcs(row + lane + 32 * j);
            s[i] += v.x*q[j].x + v.y*q[j].y + v.z*q[j].z + v.w*q[j].w;
        }
    }
#pragma unroll
    for (int o = 16; o; o >>= 1)
#pragma unroll
        for (int i = 0; i < 4; i++) s[i] += __shfl_xor_sync(~0u, s[i], o);
    if (!lane) {
#pragma unroll
        for (int i = 0; i < 4; i++)
            g_sc1[(size_t)b * (NM + 1) + 1 + k0 + i] = s[i] * (1.f / 22.f);
    }
    GRID_LAUNCH_DEP();
}

// ---------------- softmax att1 (scores O(0.1) -> no max subtraction needed) ----------------
__global__ __launch_bounds__(256) void soft1_kernel()
{
    GRID_WAIT();
    int b = blockIdx.x, t = threadIdx.x;
    __shared__ float red[256];
    __shared__ float ex[NM + 1];
    __shared__ float s0sh;
    float p = 0.f;
    for (int i = t; i < DM; i += 256) p += g_csp[b * DM + i] * g_qk1[b * DM + i];
    red[t] = p; __syncthreads();
    for (int s = 128; s; s >>= 1) { if (t < s) red[t] += red[t + s]; __syncthreads(); }
    if (t == 0) s0sh = red[0] * (1.f / 22.f);
    __syncthreads();
    float zp = 0.f;
    for (int i = t; i < NM + 1; i += 256) {
        float s = (i == 0) ? s0sh : g_sc1[b * (NM + 1) + i];
        float e = __expf(s);
        ex[i] = e; zp += e;
    }
    red[t] = zp; __syncthreads();
    for (int s = 128; s; s >>= 1) { if (t < s) red[t] += red[t + s]; __syncthreads(); }
    float inv = 1.f / red[0];
    for (int i = t; i < NM + 1; i += 256) g_att1s[b * (NM + 1) + i] = ex[i] * inv;
    GRID_LAUNCH_DEP();
}

// ---------------- att1 projection: single pass over proj_w, all 16 batches ----------------
__global__ __launch_bounds__(256) void proj_kernel(
    const float* __restrict__ proj_w, const float* __restrict__ proj_b)
{
    GRID_WAIT();
    extern __shared__ float att[];             // [BB * (NM+1)] = 65568 B
    for (int idx = threadIdx.x; idx < BB * (NM + 1); idx += 256) {
        int bb = idx / (NM + 1), i = idx - bb * (NM + 1);
        att[idx] = g_att1s[(size_t)bb * (NM + 1) + i];
    }
    __syncthreads();
    int j = blockIdx.x * 8 + (threadIdx.x >> 5);
    int lane = threadIdx.x & 31;
    if (j < NKV) {
        const float* wrow = proj_w + (size_t)j * (NM + 1);
        float acc[BB];
#pragma unroll
        for (int bb = 0; bb < BB; bb++) acc[bb] = 0.f;
        for (int i = lane; i < NM + 1; i += 32) {
            float w = __ldcs(wrow + i);
#pragma unroll
            for (int bb = 0; bb < BB; bb++) acc[bb] += w * att[bb * (NM + 1) + i];
        }
#pragma unroll
        for (int bb = 0; bb < BB; bb++) {
            float v = acc[bb];
#pragma unroll
            for (int o = 16; o; o >>= 1) v += __shfl_xor_sync(~0u, v, o);
            if (!lane) g_a1p[(size_t)bb * NKV + j] = v + proj_b[j];
        }
    }
    GRID_LAUNCH_DEP();
}

// ---------------- fused x0 pass: two-pass (batched dots, then reload-accumulate) ----------------
__global__ __launch_bounds__(256) void big_kernel(const float* __restrict__ x0)
{
    GRID_WAIT();
    int b = blockIdx.y, chunk = blockIdx.x;
    int t = threadIdx.x, warp = t >> 5, lane = t & 31;
    __shared__ float4 qk2s[256];
    __shared__ float4 Es[256], As[256];
    __shared__ float Zs[8];
    qk2s[t] = ((const float4*)(g_qk2 + (size_t)b * DL))[t];
    Es[t] = make_float4(0.f, 0.f, 0.f, 0.f);
    As[t] = make_float4(0.f, 0.f, 0.f, 0.f);
    __syncthreads();

    int k0 = chunk * 64 + warp;
    const float4* base = (const float4*)(x0 + ((size_t)b * NL + k0) * DL) + lane;

    float4 aE[8], aA[8];
#pragma unroll
    for (int j = 0; j < 8; j++) { aE[j] = make_float4(0,0,0,0); aA[j] = make_float4(0,0,0,0); }
    float zacc = 0.f;

#pragma unroll
    for (int half = 0; half < 2; half++) {
        // pass 1: 4 row-dots with full MLP (v registers die immediately)
        float s[4] = {0.f, 0.f, 0.f, 0.f};
#pragma unroll
        for (int r = 0; r < 4; r++) {
            int rr = half * 4 + r;
            const float4* row = base + (size_t)rr * 8 * 256;
#pragma unroll
            for (int j = 0; j < 8; j++) {
                float4 v = row[32 * j];
                float4 q = qk2s[lane + 32 * j];
                s[r] += v.x*q.x + v.y*q.y + v.z*q.z + v.w*q.w;
            }
        }
        // pipelined shfl reduce of 4 values
#pragma unroll
        for (int o = 16; o; o >>= 1)
#pragma unroll
            for (int r = 0; r < 4; r++) s[r] += __shfl_xor_sync(~0u, s[r], o);
        float w2[4], w1[4];
#pragma unroll
        for (int r = 0; r < 4; r++) {
            int rr = half * 4 + r;
            w2[r] = __expf(s[r] * (1.f / 32.f));
            zacc += w2[r];
            w1[r] = g_a1p[(size_t)b * NKV + k0 + rr * 8 + 1];
        }
        // pass 2: reload rows (L1/L2 hot) and accumulate
#pragma unroll
        for (int r = 0; r < 4; r++) {
            int rr = half * 4 + r;
            const float4* row = base + (size_t)rr * 8 * 256;
            float a2 = w2[r], a1 = w1[r];
#pragma unroll
            for (int j = 0; j < 8; j++) {
                float4 v = row[32 * j];
                aE[j].x += a2 * v.x; aE[j].y += a2 * v.y; aE[j].z += a2 * v.z; aE[j].w += a2 * v.w;
                aA[j].x += a1 * v.x; aA[j].y += a1 * v.y; aA[j].z += a1 * v.z; aA[j].w += a1 * v.w;
            }
        }
    }
    // deterministic block combine (serialized warps)
    for (int w = 0; w < 8; w++) {
        if (warp == w) {
#pragma unroll
            for (int j = 0; j < 8; j++) {
                int idx = lane + 32 * j;
                float4 e = Es[idx];
                e.x += aE[j].x; e.y += aE[j].y; e.z += aE[j].z; e.w += aE[j].w;
                Es[idx] = e;
                float4 a = As[idx];
                a.x += aA[j].x; a.y += aA[j].y; a.z += aA[j].z; a.w += aA[j].w;
                As[idx] = a;
            }
            if (lane == 0) Zs[w] = zacc;
        }
        __syncthreads();
    }
    ((float4*)(g_PE + ((size_t)b * NCHUNK + chunk) * DL))[t] = Es[t];
    ((float4*)(g_PA + ((size_t)b * NCHUNK + chunk) * DL))[t] = As[t];
    if (t == 0) {
        float z = 0.f;
#pragma unroll
        for (int w = 0; w < 8; w++) z += Zs[w];
        g_PZ[b * NCHUNK + chunk] = z;
    }
    GRID_LAUNCH_DEP();
}

// ---------------- combine partials + cls row + last p_l row -> u[b,d] ----------------
__global__ __launch_bounds__(1024) void u_kernel(const float* __restrict__ x0)
{
    GRID_WAIT();
    int b = blockIdx.x, d = threadIdx.x;
    __shared__ float red[1024];
    __shared__ float zsh, wl2sh;
    float cmp = g_cmp[b * DL + d];
    float qk  = g_qk2[b * DL + d];
    float xlast = x0[((size_t)b * NL + NL - 1) * DL + d];
    red[d] = cmp * qk; __syncthreads();
    for (int s = 512; s; s >>= 1) { if (d < s) red[d] += red[d + s]; __syncthreads(); }
    float ecls = __expf(red[0] * (1.f / 32.f));
    __syncthreads();
    red[d] = xlast * qk; __syncthreads();
    for (int s = 512; s; s >>= 1) { if (d < s) red[d] += red[d + s]; __syncthreads(); }
    if (d == 0) {
        float wl2 = __expf(red[0] * (1.f / 32.f));
        float z = ecls + wl2;
        for (int c = 0; c < NCHUNK; c++) z += g_PZ[b * NCHUNK + c];
        zsh = z; wl2sh = wl2;
    }
    __syncthreads();
    float e = 0.f, a = 0.f;
    for (int c = 0; c < NCHUNK; c++) {
        e += g_PE[((size_t)b * NCHUNK + c) * DL + d];
        a += g_PA[((size_t)b * NCHUNK + c) * DL + d];
    }
    float a1p0 = g_a1p[(size_t)b * NKV];
    float a1pl = g_a1p[(size_t)b * NKV + NKV - 1];
    e += wl2sh * xlast;
    a += a1pl * xlast;
    g_u[b * DL + d] = 0.3f * (a1p0 * cmp + a) + 0.7f * (ecls * cmp + e) / zsh;
    GRID_LAUNCH_DEP();
}

// ---------------- broadcast g_s to all 4097 output rows ----------------
__global__ __launch_bounds__(256) void write_kernel(float* __restrict__ out)
{
    GRID_WAIT();
    int b = blockIdx.y;
    int g = threadIdx.x >> 6, l = threadIdx.x & 63;
    float4 val = ((const float4*)(g_gs + b * DS))[l];
    int base = blockIdx.x * 32;
    float4* ob = (float4*)out + (size_t)b * NL * 64;
    int lim = base + 32; if (lim > NL) lim = NL;
    for (int r = base + g; r < lim; r += 4)
        __stcs(ob + (size_t)r * 64 + l, val);
    GRID_LAUNCH_DEP();
}

// ---------------- PDL launch helper ----------------
static cudaLaunchAttribute g_pdl_attr;

static inline void launch_pdl(const void* fn, dim3 grid, dim3 block, size_t shmem,
                              cudaStream_t st, void** args)
{
    cudaLaunchConfig_t cfg = {};
    cfg.gridDim = grid;
    cfg.blockDim = block;
    cfg.dynamicSmemBytes = shmem;
    cfg.stream = st;
    cfg.attrs = &g_pdl_attr;
    cfg.numAttrs = 1;
    cudaLaunchKernelExC(&cfg, fn, args);
}

// ---------------- launch: R11 topology (fork-join 2 streams + PDL) ----------------
extern "C" void kernel_launch(void* const* d_in, const int* in_sizes, int n_in,
                              void* d_out, int out_size)
{
    const float* x0     = (const float*)d_in[0];
    const float* x1     = (const float*)d_in[1];
    const float* x2     = (const float*)d_in[2];
    const float* f_s_w  = (const float*)d_in[3];
    const float* f_s_b  = (const float*)d_in[4];
    const float* f_m_w  = (const float*)d_in[5];
    const float* f_m_b  = (const float*)d_in[6];
    const float* Wq1    = (const float*)d_in[7];
    const float* Wk1    = (const float*)d_in[8];
    const float* Wq2    = (const float*)d_in[9];
    const float* Wk2    = (const float*)d_in[10];
    const float* Wv     = (const float*)d_in[11];
    const float* proj_w = (const float*)d_in[12];
    const float* proj_b = (const float*)d_in[13];
    const float* gs_w   = (const float*)d_in[14];
    const float* gs_b   = (const float*)d_in[15];

    static cudaStream_t s1 = nullptr, s2 = nullptr;
    static cudaEvent_t evr = nullptr, ev1 = nullptr, ev2 = nullptr;
    if (!s1) {
        cudaStreamCreateWithFlags(&s1, cudaStreamNonBlocking);
        cudaStreamCreateWithFlags(&s2, cudaStreamNonBlocking);
        cudaEventCreateWithFlags(&evr, cudaEventDisableTiming);
        cudaEventCreateWithFlags(&ev1, cudaEventDisableTiming);
        cudaEventCreateWithFlags(&ev2, cudaEventDisableTiming);
        cudaFuncSetAttribute(proj_kernel, cudaFuncAttributeMaxDynamicSharedMemorySize,
                             BB * (NM + 1) * 4);
        g_pdl_attr.id = cudaLaunchAttributeProgrammaticStreamSerialization;
        g_pdl_attr.val.programmaticStreamSerializationAllowed = 1;
    }

    float *p_csp, *p_q1, *p_qk1, *p_cmp, *p_q2, *p_qk2, *p_u, *p_outv, *p_gs, *p_part1, *p_part2;
    cudaGetSymbolAddress((void**)&p_csp,   g_csp);
    cudaGetSymbolAddress((void**)&p_q1,    g_q1);
    cudaGetSymbolAddress((void**)&p_qk1,   g_qk1);
    cudaGetSymbolAddress((void**)&p_cmp,   g_cmp);
    cudaGetSymbolAddress((void**)&p_q2,    g_q2);
    cudaGetSymbolAddress((void**)&p_qk2,   g_qk2);
    cudaGetSymbolAddress((void**)&p_u,     g_u);
    cudaGetSymbolAddress((void**)&p_outv,  g_outv);
    cudaGetSymbolAddress((void**)&p_gs,    g_gs);
    cudaGetSymbolAddress((void**)&p_part1, g_part1);
    cudaGetSymbolAddress((void**)&p_part2, g_part2);

    const float* nullb = nullptr;

    // fork
    cudaEventRecord(evr, 0);
    cudaStreamWaitEvent(s1, evr, 0);
    cudaStreamWaitEvent(s2, evr, 0);

    // Branch 1 (att1 chain): csp -> q1 -> qk1 -> score1 -> soft1 -> proj
    gemvA_kernel<<<64, 256, 0, s1>>>(f_s_w, x2, (NL * DS) / 4, f_s_b, p_csp, DM, DS);
    {
        int ld = DM / 4, M = DM, D = DM;
        void* a[] = {(void*)&Wq1, (void*)&p_csp, &ld, (void*)&nullb, (void*)&p_q1, &M, &D};
        launch_pdl((const void*)gemvA_kernel, dim3(64), dim3(256), 0, s1, a);
    }
    {
        int M = DM, D = DM;
        void* a[] = {(void*)&Wk1, (void*)&p_q1, (void*)&p_part1, &M, &D};
        launch_pdl((const void*)gemvB_kernel, dim3(2, MCH), dim3(256), 0, s1, a);
    }
    {
        int D = DM;
        void* a[] = {(void*)&p_part1, (void*)&p_qk1, &D};
        launch_pdl((const void*)gemvBred_kernel, dim3(32), dim3(256), 0, s1, a);
    }
    {
        void* a[] = {(void*)&x1};
        launch_pdl((const void*)score1_kernel, dim3((BB * NM) / 32), dim3(256), 0, s1, a);
    }
    {
        void* a[] = {nullptr};
        launch_pdl((const void*)soft1_kernel, dim3(BB), dim3(256), 0, s1, a);
    }
    {
        void* a[] = {(void*)&proj_w, (void*)&proj_b};
        launch_pdl((const void*)proj_kernel, dim3((NKV + 7) / 8), dim3(256),
                   BB * (NM + 1) * 4, s1, a);
    }

    // Branch 2 (qk2 chain): cmp -> q2 -> qk2
    gemvA_kernel<<<128, 256, 0, s2>>>(f_m_w, x1, ((NM + 1) * DM) / 4, f_m_b, p_cmp, DL, DM);
    {
        int ld = DL / 4, M = DL, D = DL;
        void* a[] = {(void*)&Wq2, (void*)&p_cmp, &ld, (void*)&nullb, (void*)&p_q2, &M, &D};
        launch_pdl((const void*)gemvA_kernel, dim3(128), dim3(256), 0, s2, a);
    }
    {
        int M = DL, D = DL;
        void* a[] = {(void*)&Wk2, (void*)&p_q2, (void*)&p_part2, &M, &D};
        launch_pdl((const void*)gemvB_kernel, dim3(4, MCH), dim3(256), 0, s2, a);
    }
    {
        int D = DL;
        void* a[] = {(void*)&p_part2, (void*)&p_qk2, &D};
        launch_pdl((const void*)gemvBred_kernel, dim3(64), dim3(256), 0, s2, a);
    }

    // join
    cudaEventRecord(ev1, s1);
    cudaEventRecord(ev2, s2);
    cudaStreamWaitEvent(0, ev1, 0);
    cudaStreamWaitEvent(0, ev2, 0);

    // main chain (big launched normally after the event join)
    big_kernel<<<dim3(NCHUNK, BB), 256>>>(x0);
    {
        void* a[] = {(void*)&x0};
        launch_pdl((const void*)u_kernel, dim3(BB), dim3(1024), 0, 0, a);
    }
    {
        int ld = DL / 4, M = DL, D = DL;
        void* a[] = {(void*)&Wv, (void*)&p_u, &ld, (void*)&nullb, (void*)&p_outv, &M, &D};
        launch_pdl((const void*)gemvA_kernel, dim3(128), dim3(256), 0, 0, a);
    }
    {
        int ld = DL / 4, M = DS, D = DL;
        void* a[] = {(void*)&gs_w, (void*)&p_outv, &ld, (void*)&gs_b, (void*)&p_gs, &M, &D};
        launch_pdl((const void*)gemvA_kernel, dim3(32), dim3(256), 0, 0, a);
    }
    {
        float* outp = (float*)d_out;
        void* a[] = {(void*)&outp};
        launch_pdl((const void*)write_kernel, dim3((NL + 31) / 32, BB), dim3(256), 0, 0, a);
    }
}

// round 15
// speedup vs baseline: 1.1229x; 1.1229x over previous
#include <cuda_runtime.h>

// Problem constants
#define BB 16
#define NL 4097          // x0 rows per batch
#define NM 1024          // p_m rows
#define DS 256
#define DM 512
#define DL 1024
#define NKV 4098         // cls + NL
#define NCHUNK 64        // big covers 64*64 = 4096 rows; row 4096 handled in u_kernel
#define MCH 32           // m-chunks for transposed gemv

// PDL device hooks
#define GRID_WAIT()       asm volatile("griddepcontrol.wait;" ::: "memory")
#define GRID_LAUNCH_DEP() asm volatile("griddepcontrol.launch_dependents;" ::: "memory")

// ---------------- device scratch ----------------
__device__ float g_csp  [BB*DM];
__device__ float g_q1   [BB*DM];
__device__ float g_qk1  [BB*DM];
__device__ float g_cmp  [BB*DL];
__device__ float g_q2   [BB*DL];
__device__ float g_qk2  [BB*DL];
__device__ float g_att1s[BB*(NM+1)];   // unnormalized exp(score/22)
__device__ float g_a1p  [BB*NKV];
__device__ float g_PE   [BB*NCHUNK*DL];
__device__ float g_PA   [BB*NCHUNK*DL];
__device__ float g_PZ   [BB*NCHUNK];
__device__ float g_u    [BB*DL];
__device__ float g_outv [BB*DL];
__device__ float g_gs   [BB*DS];
__device__ float g_part1[MCH*BB*DM];
__device__ float g_part2[MCH*BB*DL];

// ---------------- multi-batch GEMV: Y[b,m] = bias[m] + W[m,:]·X[b,:] ----------------
__global__ __launch_bounds__(256) void gemvA_kernel(
    const float* __restrict__ W, const float* __restrict__ X, int ldx4,
    const float* __restrict__ bias, float* __restrict__ Y, int M, int D)
{
    GRID_WAIT();
    int m = blockIdx.x * 8 + (threadIdx.x >> 5);
    int lane = threadIdx.x & 31;
    if (m < M) {
        const float4* w4 = (const float4*)(W + (size_t)m * D);
        const float4* x4 = (const float4*)X;
        int D4 = D >> 2;
        float acc[BB];
#pragma unroll
        for (int b = 0; b < BB; b++) acc[b] = 0.f;
        for (int f = lane; f < D4; f += 32) {
            float4 w = w4[f];
#pragma unroll
            for (int b = 0; b < BB; b++) {
                float4 x = x4[(size_t)b * ldx4 + f];
                acc[b] += w.x*x.x + w.y*x.y + w.z*x.z + w.w*x.w;
            }
        }
#pragma unroll
        for (int b = 0; b < BB; b++) {
            float v = acc[b];
#pragma unroll
            for (int o = 16; o; o >>= 1) v += __shfl_xor_sync(~0u, v, o);
            if (lane == 0) Y[(size_t)b * M + m] = v + (bias ? bias[m] : 0.f);
        }
    }
    GRID_LAUNCH_DEP();
}

// ---------------- transposed GEMV partials: part[my][b][d] ----------------
__global__ __launch_bounds__(256) void gemvB_kernel(
    const float* __restrict__ W, const float* __restrict__ X,
    float* __restrict__ part, int M, int D)
{
    GRID_WAIT();
    int d = blockIdx.x * 256 + threadIdx.x;
    int rows = M / MCH;                 // 16 or 32
    int m0 = blockIdx.y * rows;
    __shared__ float q[BB * 32];
    for (int idx = threadIdx.x; idx < BB * rows; idx += 256) {
        int bb = idx / rows, mm = idx - bb * rows;
        q[bb * rows + mm] = X[(size_t)bb * M + m0 + mm];
    }
    __syncthreads();
    float acc[BB];
#pragma unroll
    for (int b = 0; b < BB; b++) acc[b] = 0.f;
    for (int mm = 0; mm < rows; mm++) {
        float w = W[(size_t)(m0 + mm) * D + d];
#pragma unroll
        for (int b = 0; b < BB; b++) acc[b] += w * q[b * rows + mm];
    }
#pragma unroll
    for (int b = 0; b < BB; b++)
        part[((size_t)blockIdx.y * BB + b) * D + d] = acc[b];
    GRID_LAUNCH_DEP();
}

__global__ __launch_bounds__(256) void gemvBred_kernel(
    const float* __restrict__ part, float* __restrict__ Y, int D)
{
    GRID_WAIT();
    int t = blockIdx.x * 256 + threadIdx.x;
    int b = t / D, d = t - b * D;
    float acc = 0.f;
#pragma unroll
    for (int c = 0; c < MCH; c++) acc += part[((size_t)c * BB + b) * D + d];
    Y[t] = acc;
    GRID_LAUNCH_DEP();
}

// ---------------- score1e: p_m scores -> unnormalized exp; blocks >= 512 do cls ----------------
__global__ __launch_bounds__(256) void score1e_kernel(const float* __restrict__ x1)
{
    GRID_WAIT();
    int blk = blockIdx.x;
    int warp = threadIdx.x >> 5, lane = threadIdx.x & 31;
    if (blk < 512) {
        int gw = blk * 8 + warp;
        int rr = gw * 4;
        int b = rr >> 10, k0 = rr & 1023;
        const float4* qk = (const float4*)(g_qk1 + (size_t)b * DM);
        float4 q[4];
#pragma unroll
        for (int j = 0; j < 4; j++) q[j] = qk[lane + 32 * j];
#pragma unroll
        for (int i = 0; i < 4; i++) {
            const float4* row = (const float4*)(x1 + ((size_t)b * (NM + 1) + 1 + k0 + i) * DM);
            float s = 0.f;
#pragma unroll
            for (int j = 0; j < 4; j++) {
                float4 v = __ldcs(row + lane + 32 * j);
                s += v.x*q[j].x + v.y*q[j].y + v.z*q[j].z + v.w*q[j].w;
            }
#pragma unroll
            for (int o = 16; o; o >>= 1) s += __shfl_xor_sync(~0u, s, o);
            if (!lane) g_att1s[(size_t)b * (NM + 1) + 1 + k0 + i] = __expf(s * (1.f / 22.f));
        }
    } else {
        int b = (blk - 512) * 8 + warp;   // blocks 512,513 -> batches 0..15
        const float4* c4 = (const float4*)(g_csp + (size_t)b * DM);
        const float4* q4 = (const float4*)(g_qk1 + (size_t)b * DM);
        float p = 0.f;
#pragma unroll
        for (int j = 0; j < 4; j++) {
            float4 cc = c4[lane + 32 * j];
            float4 qq = q4[lane + 32 * j];
            p += cc.x*qq.x + cc.y*qq.y + cc.z*qq.z + cc.w*qq.w;
        }
#pragma unroll
        for (int o = 16; o; o >>= 1) p += __shfl_xor_sync(~0u, p, o);
        if (!lane) g_att1s[(size_t)b * (NM + 1)] = __expf(p * (1.f / 22.f));
    }
    GRID_LAUNCH_DEP();
}

// ---------------- projZ: inline 1/Z + projection, all 16 batches per block ----------------
__global__ __launch_bounds__(256) void projZ_kernel(
    const float* __restrict__ proj_w, const float* __restrict__ proj_b)
{
    GRID_WAIT();
    extern __shared__ float sm[];           // att [BB*(NM+1)] then zinv[16]
    float* att = sm;
    float* zs  = sm + BB * (NM + 1);
    int warp = threadIdx.x >> 5, lane = threadIdx.x & 31;
    for (int idx = threadIdx.x; idx < BB * (NM + 1); idx += 256) {
        int bb = idx / (NM + 1), i = idx - bb * (NM + 1);
        att[idx] = g_att1s[(size_t)bb * (NM + 1) + i];
    }
    __syncthreads();
#pragma unroll
    for (int h = 0; h < 2; h++) {           // warp w -> batches w, w+8 (deterministic)
        int bb = warp + 8 * h;
        float z = 0.f;
        for (int i = lane; i < NM + 1; i += 32) z += att[bb * (NM + 1) + i];
#pragma unroll
        for (int o = 16; o; o >>= 1) z += __shfl_xor_sync(~0u, z, o);
        if (!lane) zs[bb] = 1.f / z;
    }
    __syncthreads();
    int j = blockIdx.x * 8 + warp;
    if (j < NKV) {
        const float* wrow = proj_w + (size_t)j * (NM + 1);
        float acc[BB];
#pragma unroll
        for (int bb = 0; bb < BB; bb++) acc[bb] = 0.f;
        for (int i = lane; i < NM + 1; i += 32) {
            float w = __ldcs(wrow + i);
#pragma unroll
            for (int bb = 0; bb < BB; bb++) acc[bb] += w * att[bb * (NM + 1) + i];
        }
#pragma unroll
        for (int bb = 0; bb < BB; bb++) {
            float v = acc[bb];
#pragma unroll
            for (int o = 16; o; o >>= 1) v += __shfl_xor_sync(~0u, v, o);
            if (!lane) g_a1p[(size_t)bb * NKV + j] = v * zs[bb] + proj_b[j];
        }
    }
    GRID_LAUNCH_DEP();
}

// ---------------- fused x0 pass: single-pass register accumulation (R11 form) ----------------
__global__ __launch_bounds__(256) void big_kernel(const float* __restrict__ x0)
{
    GRID_WAIT();
    int b = blockIdx.y, chunk = blockIdx.x;
    int t = threadIdx.x, warp = t >> 5, lane = t & 31;
    __shared__ float4 qk2s[256];
    __shared__ float4 Es[256], As[256];
    __shared__ float Zs[8];
    qk2s[t] = ((const float4*)(g_qk2 + (size_t)b * DL))[t];
    Es[t] = make_float4(0.f, 0.f, 0.f, 0.f);
    As[t] = make_float4(0.f, 0.f, 0.f, 0.f);
    __syncthreads();

    float4 aE[8], aA[8];
#pragma unroll
    for (int j = 0; j < 8; j++) { aE[j] = make_float4(0,0,0,0); aA[j] = make_float4(0,0,0,0); }
    float zacc = 0.f;
    int k0 = chunk * 64 + warp;
#pragma unroll 2
    for (int rr = 0; rr < 8; rr++) {
        int k = k0 + rr * 8;
        const float4* row = (const float4*)(x0 + ((size_t)b * NL + k) * DL);
        float4 v[8];
#pragma unroll
        for (int j = 0; j < 8; j++) v[j] = __ldcs(row + lane + 32 * j);
        float s = 0.f;
#pragma unroll
        for (int j = 0; j < 8; j++) {
            float4 q = qk2s[lane + 32 * j];
            s += v[j].x*q.x + v[j].y*q.y + v[j].z*q.z + v[j].w*q.w;
        }
#pragma unroll
        for (int o = 16; o; o >>= 1) s += __shfl_xor_sync(~0u, s, o);
        float w2 = __expf(s * (1.f / 32.f));
        float w1 = g_a1p[(size_t)b * NKV + k + 1];
        zacc += w2;
#pragma unroll
        for (int j = 0; j < 8; j++) {
            aE[j].x += w2 * v[j].x; aE[j].y += w2 * v[j].y; aE[j].z += w2 * v[j].z; aE[j].w += w2 * v[j].w;
            aA[j].x += w1 * v[j].x; aA[j].y += w1 * v[j].y; aA[j].z += w1 * v[j].z; aA[j].w += w1 * v[j].w;
        }
    }
    for (int w = 0; w < 8; w++) {
        if (warp == w) {
#pragma unroll
            for (int j = 0; j < 8; j++) {
                int idx = lane + 32 * j;
                float4 e = Es[idx];
                e.x += aE[j].x; e.y += aE[j].y; e.z += aE[j].z; e.w += aE[j].w;
                Es[idx] = e;
                float4 a = As[idx];
                a.x += aA[j].x; a.y += aA[j].y; a.z += aA[j].z; a.w += aA[j].w;
                As[idx] = a;
            }
            if (lane == 0) Zs[w] = zacc;
        }
        __syncthreads();
    }
    ((float4*)(g_PE + ((size_t)b * NCHUNK + chunk) * DL))[t] = Es[t];
    ((float4*)(g_PA + ((size_t)b * NCHUNK + chunk) * DL))[t] = As[t];
    if (t == 0) {
        float z = 0.f;
#pragma unroll
        for (int w = 0; w < 8; w++) z += Zs[w];
        g_PZ[b * NCHUNK + chunk] = z;
    }
    GRID_LAUNCH_DEP();
}

// ---------------- combine partials + cls row + last p_l row -> u[b,d] ----------------
__global__ __launch_bounds__(1024) void u_kernel(const float* __restrict__ x0)
{
    GRID_WAIT();
    int b = blockIdx.x, d = threadIdx.x;
    __shared__ float red[1024];
    __shared__ float zsh, wl2sh;
    float cmp = g_cmp[b * DL + d];
    float qk  = g_qk2[b * DL + d];
    float xlast = x0[((size_t)b * NL + NL - 1) * DL + d];
    red[d] = cmp * qk; __syncthreads();
    for (int s = 512; s; s >>= 1) { if (d < s) red[d] += red[d + s]; __syncthreads(); }
    float ecls = __expf(red[0] * (1.f / 32.f));
    __syncthreads();
    red[d] = xlast * qk; __syncthreads();
    for (int s = 512; s; s >>= 1) { if (d < s) red[d] += red[d + s]; __syncthreads(); }
    if (d == 0) {
        float wl2 = __expf(red[0] * (1.f / 32.f));
        float z = ecls + wl2;
        for (int c = 0; c < NCHUNK; c++) z += g_PZ[b * NCHUNK + c];
        zsh = z; wl2sh = wl2;
    }
    __syncthreads();
    float e = 0.f, a = 0.f;
    for (int c = 0; c < NCHUNK; c++) {
        e += g_PE[((size_t)b * NCHUNK + c) * DL + d];
        a += g_PA[((size_t)b * NCHUNK + c) * DL + d];
    }
    float a1p0 = g_a1p[(size_t)b * NKV];
    float a1pl = g_a1p[(size_t)b * NKV + NKV - 1];
    e += wl2sh * xlast;
    a += a1pl * xlast;
    g_u[b * DL + d] = 0.3f * (a1p0 * cmp + a) + 0.7f * (ecls * cmp + e) / zsh;
    GRID_LAUNCH_DEP();
}

// ---------------- broadcast g_s to all 4097 output rows ----------------
__global__ __launch_bounds__(256) void write_kernel(float* __restrict__ out)
{
    GRID_WAIT();
    int b = blockIdx.y;
    int g = threadIdx.x >> 6, l = threadIdx.x & 63;
    float4 val = ((const float4*)(g_gs + b * DS))[l];
    int base = blockIdx.x * 32;
    float4* ob = (float4*)out + (size_t)b * NL * 64;
    int lim = base + 32; if (lim > NL) lim = NL;
    for (int r = base + g; r < lim; r += 4)
        __stcs(ob + (size_t)r * 64 + l, val);
    GRID_LAUNCH_DEP();
}

// ---------------- PDL launch helper ----------------
static cudaLaunchAttribute g_pdl_attr;

static inline void launch_pdl(const void* fn, dim3 grid, dim3 block, size_t shmem,
                              cudaStream_t st, void** args)
{
    cudaLaunchConfig_t cfg = {};
    cfg.gridDim = grid;
    cfg.blockDim = block;
    cfg.dynamicSmemBytes = shmem;
    cfg.stream = st;
    cfg.attrs = &g_pdl_attr;
    cfg.numAttrs = 1;
    cudaLaunchKernelExC(&cfg, fn, args);
}

// ---------------- launch: R11 topology (fork-join 2 streams + PDL) ----------------
extern "C" void kernel_launch(void* const* d_in, const int* in_sizes, int n_in,
                              void* d_out, int out_size)
{
    const float* x0     = (const float*)d_in[0];
    const float* x1     = (const float*)d_in[1];
    const float* x2     = (const float*)d_in[2];
    const float* f_s_w  = (const float*)d_in[3];
    const float* f_s_b  = (const float*)d_in[4];
    const float* f_m_w  = (const float*)d_in[5];
    const float* f_m_b  = (const float*)d_in[6];
    const float* Wq1    = (const float*)d_in[7];
    const float* Wk1    = (const float*)d_in[8];
    const float* Wq2    = (const float*)d_in[9];
    const float* Wk2    = (const float*)d_in[10];
    const float* Wv     = (const float*)d_in[11];
    const float* proj_w = (const float*)d_in[12];
    const float* proj_b = (const float*)d_in[13];
    const float* gs_w   = (const float*)d_in[14];
    const float* gs_b   = (const float*)d_in[15];

    static cudaStream_t s1 = nullptr, s2 = nullptr;
    static cudaEvent_t evr = nullptr, ev1 = nullptr, ev2 = nullptr;
    if (!s1) {
        cudaStreamCreateWithFlags(&s1, cudaStreamNonBlocking);
        cudaStreamCreateWithFlags(&s2, cudaStreamNonBlocking);
        cudaEventCreateWithFlags(&evr, cudaEventDisableTiming);
        cudaEventCreateWithFlags(&ev1, cudaEventDisableTiming);
        cudaEventCreateWithFlags(&ev2, cudaEventDisableTiming);
        cudaFuncSetAttribute(projZ_kernel, cudaFuncAttributeMaxDynamicSharedMemorySize,
                             (BB * (NM + 1) + 16) * 4);
        g_pdl_attr.id = cudaLaunchAttributeProgrammaticStreamSerialization;
        g_pdl_attr.val.programmaticStreamSerializationAllowed = 1;
    }

    float *p_csp, *p_q1, *p_qk1, *p_cmp, *p_q2, *p_qk2, *p_u, *p_outv, *p_gs, *p_part1, *p_part2;
    cudaGetSymbolAddress((void**)&p_csp,   g_csp);
    cudaGetSymbolAddress((void**)&p_q1,    g_q1);
    cudaGetSymbolAddress((void**)&p_qk1,   g_qk1);
    cudaGetSymbolAddress((void**)&p_cmp,   g_cmp);
    cudaGetSymbolAddress((void**)&p_q2,    g_q2);
    cudaGetSymbolAddress((void**)&p_qk2,   g_qk2);
    cudaGetSymbolAddress((void**)&p_u,     g_u);
    cudaGetSymbolAddress((void**)&p_outv,  g_outv);
    cudaGetSymbolAddress((void**)&p_gs,    g_gs);
    cudaGetSymbolAddress((void**)&p_part1, g_part1);
    cudaGetSymbolAddress((void**)&p_part2, g_part2);

    const float* nullb = nullptr;

    // fork
    cudaEventRecord(evr, 0);
    cudaStreamWaitEvent(s1, evr, 0);
    cudaStreamWaitEvent(s2, evr, 0);

    // Branch 1 (att1 chain): csp -> q1 -> qk1 -> score1e -> projZ
    gemvA_kernel<<<64, 256, 0, s1>>>(f_s_w, x2, (NL * DS) / 4, f_s_b, p_csp, DM, DS);
    {
        int ld = DM / 4, M = DM, D = DM;
        void* a[] = {(void*)&Wq1, (void*)&p_csp, &ld, (void*)&nullb, (void*)&p_q1, &M, &D};
        launch_pdl((const void*)gemvA_kernel, dim3(64), dim3(256), 0, s1, a);
    }
    {
        int M = DM, D = DM;
        void* a[] = {(void*)&Wk1, (void*)&p_q1, (void*)&p_part1, &M, &D};
        launch_pdl((const void*)gemvB_kernel, dim3(2, MCH), dim3(256), 0, s1, a);
    }
    {
        int D = DM;
        void* a[] = {(void*)&p_part1, (void*)&p_qk1, &D};
        launch_pdl((const void*)gemvBred_kernel, dim3(32), dim3(256), 0, s1, a);
    }
    {
        void* a[] = {(void*)&x1};
        launch_pdl((const void*)score1e_kernel, dim3(514), dim3(256), 0, s1, a);
    }
    {
        void* a[] = {(void*)&proj_w, (void*)&proj_b};
        launch_pdl((const void*)projZ_kernel, dim3((NKV + 7) / 8), dim3(256),
                   (BB * (NM + 1) + 16) * 4, s1, a);
    }

    // Branch 2 (qk2 chain): cmp -> q2 -> qk2
    gemvA_kernel<<<128, 256, 0, s2>>>(f_m_w, x1, ((NM + 1) * DM) / 4, f_m_b, p_cmp, DL, DM);
    {
        int ld = DL / 4, M = DL, D = DL;
        void* a[] = {(void*)&Wq2, (void*)&p_cmp, &ld, (void*)&nullb, (void*)&p_q2, &M, &D};
        launch_pdl((const void*)gemvA_kernel, dim3(128), dim3(256), 0, s2, a);
    }
    {
        int M = DL, D = DL;
        void* a[] = {(void*)&Wk2, (void*)&p_q2, (void*)&p_part2, &M, &D};
        launch_pdl((const void*)gemvB_kernel, dim3(4, MCH), dim3(256), 0, s2, a);
    }
    {
        int D = DL;
        void* a[] = {(void*)&p_part2, (void*)&p_qk2, &D};
        launch_pdl((const void*)gemvBred_kernel, dim3(64), dim3(256), 0, s2, a);
    }

    // join
    cudaEventRecord(ev1, s1);
    cudaEventRecord(ev2, s2);
    cudaStreamWaitEvent(0, ev1, 0);
    cudaStreamWaitEvent(0, ev2, 0);

    // main chain (big launched normally after the event join)
    big_kernel<<<dim3(NCHUNK, BB), 256>>>(x0);
    {
        void* a[] = {(void*)&x0};
        launch_pdl((const void*)u_kernel, dim3(BB), dim3(1024), 0, 0, a);
    }
    {
        int ld = DL / 4, M = DL, D = DL;
        void* a[] = {(void*)&Wv, (void*)&p_u, &ld, (void*)&nullb, (void*)&p_outv, &M, &D};
        launch_pdl((const void*)gemvA_kernel, dim3(128), dim3(256), 0, 0, a);
    }
    {
        int ld = DL / 4, M = DS, D = DL;
        void* a[] = {(void*)&gs_w, (void*)&p_outv, &ld, (void*)&gs_b, (void*)&p_gs, &M, &D};
        launch_pdl((const void*)gemvA_kernel, dim3(32), dim3(256), 0, 0, a);
    }
    {
        float* outp = (float*)d_out;
        void* a[] = {(void*)&outp};
        launch_pdl((const void*)write_kernel, dim3((NL + 31) / 32, BB), dim3(256), 0, 0, a);
    }
}